// round 6
// baseline (speedup 1.0000x reference)
#include <cuda_runtime.h>
#include <math.h>

#define Gg   256
#define Nn   512
#define Ee   4096
#define FIN  64
#define FOUT 64
#define Cc   16
#define NK   (Nn * FOUT)          // 32768 flat features per graph
#define CSRE (Ee + Nn)            // 4608 CSR entries per graph (self-loops incl)

// ---------------- scratch ----------------
__device__ float g_xw[(size_t)Gg * Nn * FOUT];     // x @ W^T
__device__ float g_h [(size_t)Gg * Nn * FOUT];     // relu(aggregate + bias)
__device__ int   g_srow [(size_t)Gg * CSRE];       // CSR source per entry
__device__ float g_snorm[(size_t)Gg * CSRE];       // CSR norm per entry
__device__ int   g_offx [(size_t)Gg * (Nn + 1)];   // CSR row offsets
__device__ float g_logits[(size_t)Gg * Cc];        // split-K partial logits

// ---------------------------------------------------------------------------
// kA (fat kernel, 512 thr):
//   blocks [0, Gg)        : per-graph CSR build -> global scratch (once)
//   blocks [Gg, Gg+4*Gg)  : GEMM xw[g] = x[g] @ W^T, 128-node x 64-out tiles
// Both roles run concurrently; CSR work hides under GEMM occupancy.
// ---------------------------------------------------------------------------
#define XP 132                                   // Xt pitch (16B-aligned, padded)
#define KA_SMEM ((64 * XP + 64 * 68) * 4)        // 51200 B

__global__ __launch_bounds__(512) void kA(const float* __restrict__ x,
                                          const float* __restrict__ w,
                                          const int*   __restrict__ ei)
{
    extern __shared__ float sm[];
    const int tid = threadIdx.x;

    if (blockIdx.x < Gg) {
        // ---------------- CSR build for graph g ----------------
        int*   cnt  = (int*)sm;            // [512]
        int*   sc   = cnt + Nn;            // [512]
        float* dv   = (float*)(sc + Nn);   // [512]
        int*   wcur = (int*)(dv + Nn);     // [512]

        const int g = blockIdx.x;
        const int* rowp = ei + (size_t)g * 2 * Ee;
        const int* colp = rowp + Ee;

        cnt[tid] = 1;                      // self-loop
        __syncthreads();
        for (int e = tid; e < Ee; e += 512)
            atomicAdd(&cnt[colp[e]], 1);
        __syncthreads();

        const int myc = cnt[tid];
        dv[tid] = rsqrtf((float)myc);
        sc[tid] = myc;
        __syncthreads();

        for (int s = 1; s < Nn; s <<= 1) {
            int v = (tid >= s) ? sc[tid - s] : 0;
            __syncthreads();
            sc[tid] += v;
            __syncthreads();
        }
        const int incl = sc[tid];
        const int excl = incl - myc;

        g_offx[(size_t)g * (Nn + 1) + tid + 1] = incl;
        if (tid == 0) g_offx[(size_t)g * (Nn + 1)] = 0;
        if (tid < Cc) g_logits[g * Cc + tid] = 0.f;

        const size_t base = (size_t)g * CSRE;
        g_srow [base + excl] = tid;        // self-loop entry first
        g_snorm[base + excl] = dv[tid] * dv[tid];
        wcur[tid] = excl + 1;
        __syncthreads();

        for (int e = tid; e < Ee; e += 512) {
            int r = rowp[e], c = colp[e];
            int pos = atomicAdd(&wcur[c], 1);
            g_srow [base + pos] = r;
            g_snorm[base + pos] = dv[r] * dv[c];
        }
    } else {
        // ---------------- GEMM tile: 128 nodes x 64 outs, 4x4/thread --------
        float* Xt = sm;                    // [64][XP]   Xt[k][n]
        float* Wt = sm + 64 * XP;          // [64][68]   Wt[k][o]

        const int b  = blockIdx.x - Gg;
        const int g  = b >> 2;
        const int nb = (b & 3) * 128;

        const float* xg = x + ((size_t)g * Nn + nb) * FIN;

        for (int i = tid; i < 128 * 64; i += 512) {
            int r = i >> 6, k = i & 63;
            Xt[k * XP + r] = xg[r * FIN + k];
        }
        for (int i = tid; i < 64 * 64; i += 512) {
            int o = i >> 6, k = i & 63;
            Wt[k * 68 + o] = w[o * FIN + k];
        }
        __syncthreads();

        const int o0 = (tid & 15) * 4;
        const int n0 = (tid >> 4) * 4;

        float acc[4][4];
        #pragma unroll
        for (int i = 0; i < 4; i++)
            #pragma unroll
            for (int j = 0; j < 4; j++) acc[i][j] = 0.f;

        #pragma unroll 8
        for (int k = 0; k < 64; k++) {
            float4 xv = *(const float4*)&Xt[k * XP + n0];
            float4 wv = *(const float4*)&Wt[k * 68 + o0];
            float xs[4] = {xv.x, xv.y, xv.z, xv.w};
            float ws[4] = {wv.x, wv.y, wv.z, wv.w};
            #pragma unroll
            for (int i = 0; i < 4; i++)
                #pragma unroll
                for (int j = 0; j < 4; j++)
                    acc[i][j] = fmaf(xs[i], ws[j], acc[i][j]);
        }

        float* op = g_xw + ((size_t)g * Nn + nb) * FOUT;
        #pragma unroll
        for (int i = 0; i < 4; i++)
            *(float4*)&op[(size_t)(n0 + i) * FOUT + o0] =
                make_float4(acc[i][0], acc[i][1], acc[i][2], acc[i][3]);
    }
}

// ---------------------------------------------------------------------------
// K2b: pure aggregation from global CSR. ZERO smem -> full L1D, 8 blocks/SM.
//      grid (G, 4) x 256 thr; warp-per-node, quad accumulators (MLP=4).
// ---------------------------------------------------------------------------
__global__ __launch_bounds__(256) void k2b_agg(const float* __restrict__ conv_bias)
{
    const int g   = blockIdx.x;
    const int q   = blockIdx.y;            // quarter 0..3
    const int tid = threadIdx.x;
    const int wid  = tid >> 5;
    const int lane = tid & 31;

    const float2* xw2   = (const float2*)(g_xw + (size_t)g * NK);
    float2*       h2    = (float2*)      (g_h  + (size_t)g * NK);
    const int*    offx  = g_offx  + (size_t)g * (Nn + 1) + q * 128;
    const int*    srow  = g_srow  + (size_t)g * CSRE;
    const float*  snorm = g_snorm + (size_t)g * CSRE;

    const float bx0 = __ldg(&conv_bias[lane * 2]);
    const float bx1 = __ldg(&conv_bias[lane * 2 + 1]);

    for (int ln = wid; ln < 128; ln += 8) {
        const int n  = q * 128 + ln;
        const int b  = __ldg(&offx[ln]);
        const int e2 = __ldg(&offx[ln + 1]);

        float a0x = 0.f, a0y = 0.f, a1x = 0.f, a1y = 0.f;
        float a2x = 0.f, a2y = 0.f, a3x = 0.f, a3y = 0.f;
        int j = b;
        for (; j + 4 <= e2; j += 4) {
            int   r0 = __ldg(&srow[j]),    r1 = __ldg(&srow[j+1]);
            int   r2 = __ldg(&srow[j+2]),  r3 = __ldg(&srow[j+3]);
            float m0 = __ldg(&snorm[j]),   m1 = __ldg(&snorm[j+1]);
            float m2 = __ldg(&snorm[j+2]), m3 = __ldg(&snorm[j+3]);
            float2 v0 = __ldg(&xw2[r0 * 32 + lane]);
            float2 v1 = __ldg(&xw2[r1 * 32 + lane]);
            float2 v2 = __ldg(&xw2[r2 * 32 + lane]);
            float2 v3 = __ldg(&xw2[r3 * 32 + lane]);
            a0x = fmaf(v0.x, m0, a0x);  a0y = fmaf(v0.y, m0, a0y);
            a1x = fmaf(v1.x, m1, a1x);  a1y = fmaf(v1.y, m1, a1y);
            a2x = fmaf(v2.x, m2, a2x);  a2y = fmaf(v2.y, m2, a2y);
            a3x = fmaf(v3.x, m3, a3x);  a3y = fmaf(v3.y, m3, a3y);
        }
        for (; j < e2; j++) {
            int   r  = __ldg(&srow[j]);
            float nm = __ldg(&snorm[j]);
            float2 v = __ldg(&xw2[r * 32 + lane]);
            a0x = fmaf(v.x, nm, a0x);  a0y = fmaf(v.y, nm, a0y);
        }
        float ax = (a0x + a1x) + (a2x + a3x);
        float ay = (a0y + a1y) + (a2y + a3y);
        ax = fmaxf(ax + bx0, 0.f);
        ay = fmaxf(ay + bx1, 0.f);
        h2[n * 32 + lane] = make_float2(ax, ay);
    }
}

// ---------------------------------------------------------------------------
// K3: logits += h[G,32768] @ lw[C,32768]^T   (unchanged from R4)
// ---------------------------------------------------------------------------
__global__ __launch_bounds__(256) void k3_cls(const float* __restrict__ lw)
{
    __shared__ float red[8][32];

    const int tid  = threadIdx.x;
    const int wid  = tid >> 5;
    const int lane = tid & 31;

    const int ggrp = wid & 3;
    const int kq   = wid >> 2;
    const int g0   = blockIdx.y * 8 + ggrp * 2;

    const int k4w = blockIdx.x * 512 + kq * 256;

    const float4* h4a = (const float4*)(g_h + (size_t)(g0    ) * NK);
    const float4* h4b = (const float4*)(g_h + (size_t)(g0 + 1) * NK);
    const float4* lw4 = (const float4*)lw;

    float acc[2][Cc];
    #pragma unroll
    for (int p = 0; p < 2; p++)
        #pragma unroll
        for (int c = 0; c < Cc; c++) acc[p][c] = 0.f;

    #pragma unroll 2
    for (int j = 0; j < 8; j++) {
        const int k4 = k4w + j * 32 + lane;
        float4 ha = __ldg(&h4a[k4]);
        float4 hb = __ldg(&h4b[k4]);
        #pragma unroll
        for (int c = 0; c < Cc; c++) {
            float4 wv = __ldg(&lw4[(size_t)c * (NK / 4) + k4]);
            acc[0][c] = fmaf(ha.x, wv.x, fmaf(ha.y, wv.y,
                        fmaf(ha.z, wv.z, fmaf(ha.w, wv.w, acc[0][c]))));
            acc[1][c] = fmaf(hb.x, wv.x, fmaf(hb.y, wv.y,
                        fmaf(hb.z, wv.z, fmaf(hb.w, wv.w, acc[1][c]))));
        }
    }

    #pragma unroll
    for (int p = 0; p < 2; p++)
        #pragma unroll
        for (int c = 0; c < Cc; c++) {
            float v = acc[p][c];
            #pragma unroll
            for (int o = 16; o > 0; o >>= 1)
                v += __shfl_xor_sync(0xffffffffu, v, o);
            acc[p][c] = v;
        }

    if (lane == 0) {
        #pragma unroll
        for (int p = 0; p < 2; p++)
            #pragma unroll
            for (int c = 0; c < Cc; c++)
                red[wid][p * Cc + c] = acc[p][c];
    }
    __syncthreads();

    if (tid < 128) {
        const int gi = tid >> 4;
        const int c  = tid & 15;
        const int gg = gi >> 1;
        const int p  = gi & 1;
        float s = red[gg][p * Cc + c] + red[gg + 4][p * Cc + c];
        atomicAdd(&g_logits[(size_t)(blockIdx.y * 8 + gi) * Cc + c], s);
    }
}

// ---------------------------------------------------------------------------
// K4: bias + log_softmax over [G, 16]
// ---------------------------------------------------------------------------
__global__ __launch_bounds__(256) void k4_lsm(const float* __restrict__ lb,
                                              float* __restrict__ out)
{
    const int tid = threadIdx.x;
    const int g   = blockIdx.x * 16 + (tid >> 4);
    const int c   = tid & 15;

    float s = g_logits[g * Cc + c] + lb[c];
    float m = s;
    #pragma unroll
    for (int o = 8; o > 0; o >>= 1)
        m = fmaxf(m, __shfl_xor_sync(0xffffffffu, m, o, 16));
    float se = expf(s - m);
    #pragma unroll
    for (int o = 8; o > 0; o >>= 1)
        se += __shfl_xor_sync(0xffffffffu, se, o, 16);
    out[g * Cc + c] = (s - m) - logf(se);
}

// ---------------------------------------------------------------------------
extern "C" void kernel_launch(void* const* d_in, const int* in_sizes, int n_in,
                              void* d_out, int out_size)
{
    const float* x  = (const float*)d_in[0];   // [G, N, F_IN]
    const int*   ei = (const int*)  d_in[1];   // [G, 2, E]
    const float* cw = (const float*)d_in[2];   // [F_OUT, F_IN]
    const float* cb = (const float*)d_in[3];   // [F_OUT]
    const float* lw = (const float*)d_in[4];   // [C, N*F_OUT]
    const float* lb = (const float*)d_in[5];   // [C]
    float* out = (float*)d_out;                // [G, C]

    cudaFuncSetAttribute(kA, cudaFuncAttributeMaxDynamicSharedMemorySize,
                         KA_SMEM);

    kA     <<<Gg + Gg * 4, 512, KA_SMEM>>>(x, cw, ei);
    k2b_agg<<<dim3(Gg, 4), 256>>>(cb);
    k3_cls <<<dim3(16, Gg / 8), 256>>>(lw);
    k4_lsm <<<Gg / 16, 256>>>(lb, out);
}

// round 8
// speedup vs baseline: 1.0664x; 1.0664x over previous
#include <cuda_runtime.h>
#include <cuda_bf16.h>
#include <math.h>
#include <cstdint>

#define Gg   256
#define Nn   512
#define Ee   4096
#define FIN  64
#define FOUT 64
#define Cc   16
#define NK   (Nn * FOUT)          // 32768 flat features per graph
#define CSRE (Ee + Nn)            // 4608 CSR entries per graph

// ---------------- scratch ----------------
__device__ float g_xw[(size_t)Gg * Nn * FOUT];     // x @ W^T
__device__ float g_h [(size_t)Gg * Nn * FOUT];     // relu(aggregate + bias)
__device__ int   g_srow [(size_t)Gg * CSRE];
__device__ float g_snorm[(size_t)Gg * CSRE];
__device__ int   g_offx [(size_t)Gg * (Nn + 1)];
__device__ float g_logits[(size_t)Gg * Cc];

// ===========================================================================
// K0: per-graph CSR build (self-loop first entry per row)
// ===========================================================================
__global__ __launch_bounds__(512) void k0_csr(const int* __restrict__ ei)
{
    __shared__ int   cnt[Nn];
    __shared__ int   sc[Nn];
    __shared__ float dv[Nn];
    __shared__ int   wcur[Nn];

    const int g   = blockIdx.x;
    const int tid = threadIdx.x;
    const int* rowp = ei + (size_t)g * 2 * Ee;
    const int* colp = rowp + Ee;

    cnt[tid] = 1;
    __syncthreads();
    for (int e = tid; e < Ee; e += 512)
        atomicAdd(&cnt[colp[e]], 1);
    __syncthreads();

    const int myc = cnt[tid];
    dv[tid] = rsqrtf((float)myc);
    sc[tid] = myc;
    __syncthreads();

    for (int s = 1; s < Nn; s <<= 1) {
        int v = (tid >= s) ? sc[tid - s] : 0;
        __syncthreads();
        sc[tid] += v;
        __syncthreads();
    }
    const int incl = sc[tid];
    const int excl = incl - myc;

    g_offx[(size_t)g * (Nn + 1) + tid + 1] = incl;
    if (tid == 0) g_offx[(size_t)g * (Nn + 1)] = 0;
    if (tid < Cc) g_logits[g * Cc + tid] = 0.f;

    const size_t base = (size_t)g * CSRE;
    g_srow [base + excl] = tid;
    g_snorm[base + excl] = dv[tid] * dv[tid];
    wcur[tid] = excl + 1;
    __syncthreads();

    for (int e = tid; e < Ee; e += 512) {
        int r = rowp[e], c = colp[e];
        int pos = atomicAdd(&wcur[c], 1);
        g_srow [base + pos] = r;
        g_snorm[base + pos] = dv[r] * dv[c];
    }
}

// ===========================================================================
// K1: xw = x @ W^T on the TENSOR pipe via mma.sync (bf16 hi/lo split, f32 acc)
//     CTA = 128 nodes x 64 outs, K=64. 8 warps, warp = 16 rows x 64 outs.
//     A fragments loaded directly from gmem (float2/lane, full sectors),
//     W in smem as bf16 hi/lo, pitch 72 -> conflict-free b32 fragment reads.
//     D = Ahi@Whi + Ahi@Wlo + Alo@Whi  (error ~1e-5)
// ===========================================================================
#define WP 72   // W smem pitch in bf16 elems (gq*36+t words mod 32 all distinct)

#define MMA16816(d, a, b0, b1)                                              \
    asm volatile("mma.sync.aligned.m16n8k16.row.col.f32.bf16.bf16.f32 "     \
        "{%0,%1,%2,%3}, {%4,%5,%6,%7}, {%8,%9}, {%0,%1,%2,%3};"             \
        : "+f"((d)[0]), "+f"((d)[1]), "+f"((d)[2]), "+f"((d)[3])            \
        : "r"((a)[0]), "r"((a)[1]), "r"((a)[2]), "r"((a)[3]),               \
          "r"(b0), "r"(b1))

__device__ __forceinline__ void cvt_hilo(float2 v, uint32_t& hi, uint32_t& lo)
{
    __nv_bfloat16 hx = __float2bfloat16_rn(v.x);
    __nv_bfloat16 hy = __float2bfloat16_rn(v.y);
    __nv_bfloat16 lx = __float2bfloat16_rn(v.x - __bfloat162float(hx));
    __nv_bfloat16 ly = __float2bfloat16_rn(v.y - __bfloat162float(hy));
    hi = (uint32_t)__bfloat16_as_ushort(hx) | ((uint32_t)__bfloat16_as_ushort(hy) << 16);
    lo = (uint32_t)__bfloat16_as_ushort(lx) | ((uint32_t)__bfloat16_as_ushort(ly) << 16);
}

__global__ __launch_bounds__(256) void k1_mma(const float* __restrict__ x,
                                              const float* __restrict__ w)
{
    __shared__ __align__(16) __nv_bfloat16 Whi[FOUT][WP];
    __shared__ __align__(16) __nv_bfloat16 Wlo[FOUT][WP];

    const int tid  = threadIdx.x;
    const int wid  = tid >> 5;
    const int lane = tid & 31;
    const int gq   = lane >> 2;      // row group 0..7
    const int t    = lane & 3;       // k pair   0..3

    const int g  = blockIdx.x >> 2;
    const int nb = (blockIdx.x & 3) * 128;

    // ---- W -> smem hi/lo bf16 ----
    for (int i = tid; i < FOUT * FIN; i += 256) {
        int o = i >> 6, k = i & 63;
        float v = w[i];
        __nv_bfloat16 hb = __float2bfloat16_rn(v);
        Whi[o][k] = hb;
        Wlo[o][k] = __float2bfloat16_rn(v - __bfloat162float(hb));
    }
    __syncthreads();

    const int row0 = nb + wid * 16 + gq;     // this thread's A row (and +8)
    const float* xg = x + (size_t)g * Nn * FIN;

    float acc[8][4];
    #pragma unroll
    for (int nt = 0; nt < 8; nt++)
        #pragma unroll
        for (int i = 0; i < 4; i++) acc[nt][i] = 0.f;

    #pragma unroll
    for (int c = 0; c < 4; c++) {
        const int kb = c * 16;
        // A fragments straight from gmem
        float2 v00 = __ldg((const float2*)&xg[(size_t)(row0    ) * FIN + kb +     2 * t]);
        float2 v10 = __ldg((const float2*)&xg[(size_t)(row0 + 8) * FIN + kb +     2 * t]);
        float2 v01 = __ldg((const float2*)&xg[(size_t)(row0    ) * FIN + kb + 8 + 2 * t]);
        float2 v11 = __ldg((const float2*)&xg[(size_t)(row0 + 8) * FIN + kb + 8 + 2 * t]);
        uint32_t ahi[4], alo[4];
        cvt_hilo(v00, ahi[0], alo[0]);
        cvt_hilo(v10, ahi[1], alo[1]);
        cvt_hilo(v01, ahi[2], alo[2]);
        cvt_hilo(v11, ahi[3], alo[3]);

        #pragma unroll
        for (int nt = 0; nt < 8; nt++) {
            const int n = nt * 8 + gq;
            uint32_t bh0 = *(const uint32_t*)&Whi[n][kb +     2 * t];
            uint32_t bh1 = *(const uint32_t*)&Whi[n][kb + 8 + 2 * t];
            uint32_t bl0 = *(const uint32_t*)&Wlo[n][kb +     2 * t];
            uint32_t bl1 = *(const uint32_t*)&Wlo[n][kb + 8 + 2 * t];
            MMA16816(acc[nt], ahi, bh0, bh1);
            MMA16816(acc[nt], ahi, bl0, bl1);
            MMA16816(acc[nt], alo, bh0, bh1);
        }
    }

    // ---- epilogue: C frag (c0,c1)=row gq, (c2,c3)=row gq+8, cols 2t,2t+1 ----
    float* op = g_xw + (size_t)g * NK;
    #pragma unroll
    for (int nt = 0; nt < 8; nt++) {
        const int col = nt * 8 + 2 * t;
        *(float2*)&op[(size_t)(row0    ) * FOUT + col] = make_float2(acc[nt][0], acc[nt][1]);
        *(float2*)&op[(size_t)(row0 + 8) * FOUT + col] = make_float2(acc[nt][2], acc[nt][3]);
    }
}

// ===========================================================================
// K2b: aggregation from global CSR (zero smem). grid (G,4) x 256 thr.
// ===========================================================================
__global__ __launch_bounds__(256) void k2b_agg(const float* __restrict__ conv_bias)
{
    const int g   = blockIdx.x;
    const int q   = blockIdx.y;
    const int tid = threadIdx.x;
    const int wid  = tid >> 5;
    const int lane = tid & 31;

    const float2* xw2   = (const float2*)(g_xw + (size_t)g * NK);
    float2*       h2    = (float2*)      (g_h  + (size_t)g * NK);
    const int*    offx  = g_offx  + (size_t)g * (Nn + 1) + q * 128;
    const int*    srow  = g_srow  + (size_t)g * CSRE;
    const float*  snorm = g_snorm + (size_t)g * CSRE;

    const float bx0 = __ldg(&conv_bias[lane * 2]);
    const float bx1 = __ldg(&conv_bias[lane * 2 + 1]);

    for (int ln = wid; ln < 128; ln += 8) {
        const int n  = q * 128 + ln;
        const int b  = __ldg(&offx[ln]);
        const int e2 = __ldg(&offx[ln + 1]);

        float a0x = 0.f, a0y = 0.f, a1x = 0.f, a1y = 0.f;
        float a2x = 0.f, a2y = 0.f, a3x = 0.f, a3y = 0.f;
        int j = b;
        for (; j + 4 <= e2; j += 4) {
            int   r0 = __ldg(&srow[j]),    r1 = __ldg(&srow[j+1]);
            int   r2 = __ldg(&srow[j+2]),  r3 = __ldg(&srow[j+3]);
            float m0 = __ldg(&snorm[j]),   m1 = __ldg(&snorm[j+1]);
            float m2 = __ldg(&snorm[j+2]), m3 = __ldg(&snorm[j+3]);
            float2 v0 = __ldg(&xw2[r0 * 32 + lane]);
            float2 v1 = __ldg(&xw2[r1 * 32 + lane]);
            float2 v2 = __ldg(&xw2[r2 * 32 + lane]);
            float2 v3 = __ldg(&xw2[r3 * 32 + lane]);
            a0x = fmaf(v0.x, m0, a0x);  a0y = fmaf(v0.y, m0, a0y);
            a1x = fmaf(v1.x, m1, a1x);  a1y = fmaf(v1.y, m1, a1y);
            a2x = fmaf(v2.x, m2, a2x);  a2y = fmaf(v2.y, m2, a2y);
            a3x = fmaf(v3.x, m3, a3x);  a3y = fmaf(v3.y, m3, a3y);
        }
        for (; j < e2; j++) {
            int   r  = __ldg(&srow[j]);
            float nm = __ldg(&snorm[j]);
            float2 v = __ldg(&xw2[r * 32 + lane]);
            a0x = fmaf(v.x, nm, a0x);  a0y = fmaf(v.y, nm, a0y);
        }
        float ax = (a0x + a1x) + (a2x + a3x);
        float ay = (a0y + a1y) + (a2y + a3y);
        ax = fmaxf(ax + bx0, 0.f);
        ay = fmaxf(ay + bx1, 0.f);
        h2[n * 32 + lane] = make_float2(ax, ay);
    }
}

// ===========================================================================
// K3: logits += h @ lw^T   (unchanged, R4-proven)
// ===========================================================================
__global__ __launch_bounds__(256) void k3_cls(const float* __restrict__ lw)
{
    __shared__ float red[8][32];

    const int tid  = threadIdx.x;
    const int wid  = tid >> 5;
    const int lane = tid & 31;

    const int ggrp = wid & 3;
    const int kq   = wid >> 2;
    const int g0   = blockIdx.y * 8 + ggrp * 2;
    const int k4w  = blockIdx.x * 512 + kq * 256;

    const float4* h4a = (const float4*)(g_h + (size_t)(g0    ) * NK);
    const float4* h4b = (const float4*)(g_h + (size_t)(g0 + 1) * NK);
    const float4* lw4 = (const float4*)lw;

    float acc[2][Cc];
    #pragma unroll
    for (int p = 0; p < 2; p++)
        #pragma unroll
        for (int c = 0; c < Cc; c++) acc[p][c] = 0.f;

    #pragma unroll 2
    for (int j = 0; j < 8; j++) {
        const int k4 = k4w + j * 32 + lane;
        float4 ha = __ldg(&h4a[k4]);
        float4 hb = __ldg(&h4b[k4]);
        #pragma unroll
        for (int c = 0; c < Cc; c++) {
            float4 wv = __ldg(&lw4[(size_t)c * (NK / 4) + k4]);
            acc[0][c] = fmaf(ha.x, wv.x, fmaf(ha.y, wv.y,
                        fmaf(ha.z, wv.z, fmaf(ha.w, wv.w, acc[0][c]))));
            acc[1][c] = fmaf(hb.x, wv.x, fmaf(hb.y, wv.y,
                        fmaf(hb.z, wv.z, fmaf(hb.w, wv.w, acc[1][c]))));
        }
    }

    #pragma unroll
    for (int p = 0; p < 2; p++)
        #pragma unroll
        for (int c = 0; c < Cc; c++) {
            float v = acc[p][c];
            #pragma unroll
            for (int o = 16; o > 0; o >>= 1)
                v += __shfl_xor_sync(0xffffffffu, v, o);
            acc[p][c] = v;
        }

    if (lane == 0) {
        #pragma unroll
        for (int p = 0; p < 2; p++)
            #pragma unroll
            for (int c = 0; c < Cc; c++)
                red[wid][p * Cc + c] = acc[p][c];
    }
    __syncthreads();

    if (tid < 128) {
        const int gi = tid >> 4;
        const int c  = tid & 15;
        const int gg = gi >> 1;
        const int p  = gi & 1;
        float s = red[gg][p * Cc + c] + red[gg + 4][p * Cc + c];
        atomicAdd(&g_logits[(size_t)(blockIdx.y * 8 + gi) * Cc + c], s);
    }
}

// ===========================================================================
// K4: bias + log_softmax
// ===========================================================================
__global__ __launch_bounds__(256) void k4_lsm(const float* __restrict__ lb,
                                              float* __restrict__ out)
{
    const int tid = threadIdx.x;
    const int g   = blockIdx.x * 16 + (tid >> 4);
    const int c   = tid & 15;

    float s = g_logits[g * Cc + c] + lb[c];
    float m = s;
    #pragma unroll
    for (int o = 8; o > 0; o >>= 1)
        m = fmaxf(m, __shfl_xor_sync(0xffffffffu, m, o, 16));
    float se = expf(s - m);
    #pragma unroll
    for (int o = 8; o > 0; o >>= 1)
        se += __shfl_xor_sync(0xffffffffu, se, o, 16);
    out[g * Cc + c] = (s - m) - logf(se);
}

// ===========================================================================
extern "C" void kernel_launch(void* const* d_in, const int* in_sizes, int n_in,
                              void* d_out, int out_size)
{
    const float* x  = (const float*)d_in[0];   // [G, N, F_IN]
    const int*   ei = (const int*)  d_in[1];   // [G, 2, E]
    const float* cw = (const float*)d_in[2];   // [F_OUT, F_IN]
    const float* cb = (const float*)d_in[3];   // [F_OUT]
    const float* lw = (const float*)d_in[4];   // [C, N*F_OUT]
    const float* lb = (const float*)d_in[5];   // [C]
    float* out = (float*)d_out;                // [G, C]

    k0_csr <<<Gg, 512>>>(ei);
    k1_mma <<<Gg * 4, 256>>>(x, cw);
    k2b_agg<<<dim3(Gg, 4), 256>>>(cb);
    k3_cls <<<dim3(16, Gg / 8), 256>>>(lw);
    k4_lsm <<<Gg / 16, 256>>>(lb, out);
}

// round 9
// speedup vs baseline: 1.0706x; 1.0039x over previous
#include <cuda_runtime.h>
#include <cuda_bf16.h>
#include <cuda_fp16.h>
#include <math.h>
#include <cstdint>

#define Gg   256
#define Nn   512
#define Ee   4096
#define FIN  64
#define FOUT 64
#define Cc   16
#define NK   (Nn * FOUT)          // 32768 flat features per graph
#define CSRE (Ee + Nn)            // 4608 CSR entries per graph
#define KS   16                   // k3 ksplit blocks
#define GT   32                   // k3 graph tiles (8 graphs each)

// ---------------- scratch ----------------
__device__ __half g_xw[(size_t)Gg * NK];           // x @ W^T  (fp16)
__device__ float  g_h [(size_t)Gg * NK];           // relu(aggregate + bias)
__device__ __half g_lwh[(size_t)Cc * NK];          // lin_weight in fp16
__device__ int    g_srow [(size_t)Gg * CSRE];
__device__ float  g_snorm[(size_t)Gg * CSRE];
__device__ int    g_offx [(size_t)Gg * (Nn + 1)];
__device__ float  g_logits[(size_t)Gg * Cc];
__device__ int    g_cnt[GT];                       // k3 completion counters

// ===========================================================================
// K0: per-graph CSR build + lw fp16 conversion + counter/logits reset
// ===========================================================================
__global__ __launch_bounds__(512) void k0_csr(const int*   __restrict__ ei,
                                              const float* __restrict__ lw)
{
    __shared__ int   cnt[Nn];
    __shared__ int   sc[Nn];
    __shared__ float dv[Nn];
    __shared__ int   wcur[Nn];

    const int g   = blockIdx.x;
    const int tid = threadIdx.x;
    const int* rowp = ei + (size_t)g * 2 * Ee;
    const int* colp = rowp + Ee;

    // lw -> fp16 (each block converts its 2048-element slice)
    {
        const size_t base = (size_t)g * 2048;
        for (int i = tid; i < 2048; i += 512)
            g_lwh[base + i] = __float2half_rn(lw[base + i]);
    }
    if (g == 0 && tid < GT) g_cnt[tid] = 0;
    if (tid < Cc) g_logits[g * Cc + tid] = 0.f;

    cnt[tid] = 1;
    __syncthreads();
    for (int e = tid; e < Ee; e += 512)
        atomicAdd(&cnt[colp[e]], 1);
    __syncthreads();

    const int myc = cnt[tid];
    dv[tid] = rsqrtf((float)myc);
    sc[tid] = myc;
    __syncthreads();

    for (int s = 1; s < Nn; s <<= 1) {
        int v = (tid >= s) ? sc[tid - s] : 0;
        __syncthreads();
        sc[tid] += v;
        __syncthreads();
    }
    const int incl = sc[tid];
    const int excl = incl - myc;

    g_offx[(size_t)g * (Nn + 1) + tid + 1] = incl;
    if (tid == 0) g_offx[(size_t)g * (Nn + 1)] = 0;

    const size_t base = (size_t)g * CSRE;
    g_srow [base + excl] = tid;
    g_snorm[base + excl] = dv[tid] * dv[tid];
    wcur[tid] = excl + 1;
    __syncthreads();

    for (int e = tid; e < Ee; e += 512) {
        int r = rowp[e], c = colp[e];
        int pos = atomicAdd(&wcur[c], 1);
        g_srow [base + pos] = r;
        g_snorm[base + pos] = dv[r] * dv[c];
    }
}

// ===========================================================================
// K1: xw = x @ W^T via mma.sync bf16 hi/lo (tensor pipe), epilogue -> fp16
// ===========================================================================
#define WP 72

#define MMA16816(d, a, b0, b1)                                              \
    asm volatile("mma.sync.aligned.m16n8k16.row.col.f32.bf16.bf16.f32 "     \
        "{%0,%1,%2,%3}, {%4,%5,%6,%7}, {%8,%9}, {%0,%1,%2,%3};"             \
        : "+f"((d)[0]), "+f"((d)[1]), "+f"((d)[2]), "+f"((d)[3])            \
        : "r"((a)[0]), "r"((a)[1]), "r"((a)[2]), "r"((a)[3]),               \
          "r"(b0), "r"(b1))

__device__ __forceinline__ void cvt_hilo(float2 v, uint32_t& hi, uint32_t& lo)
{
    __nv_bfloat16 hx = __float2bfloat16_rn(v.x);
    __nv_bfloat16 hy = __float2bfloat16_rn(v.y);
    __nv_bfloat16 lx = __float2bfloat16_rn(v.x - __bfloat162float(hx));
    __nv_bfloat16 ly = __float2bfloat16_rn(v.y - __bfloat162float(hy));
    hi = (uint32_t)__bfloat16_as_ushort(hx) | ((uint32_t)__bfloat16_as_ushort(hy) << 16);
    lo = (uint32_t)__bfloat16_as_ushort(lx) | ((uint32_t)__bfloat16_as_ushort(ly) << 16);
}

__global__ __launch_bounds__(256) void k1_mma(const float* __restrict__ x,
                                              const float* __restrict__ w)
{
    __shared__ __align__(16) __nv_bfloat16 Whi[FOUT][WP];
    __shared__ __align__(16) __nv_bfloat16 Wlo[FOUT][WP];

    const int tid  = threadIdx.x;
    const int wid  = tid >> 5;
    const int lane = tid & 31;
    const int gq   = lane >> 2;
    const int t    = lane & 3;

    const int g  = blockIdx.x >> 2;
    const int nb = (blockIdx.x & 3) * 128;

    for (int i = tid; i < FOUT * FIN; i += 256) {
        int o = i >> 6, k = i & 63;
        float v = w[i];
        __nv_bfloat16 hb = __float2bfloat16_rn(v);
        Whi[o][k] = hb;
        Wlo[o][k] = __float2bfloat16_rn(v - __bfloat162float(hb));
    }
    __syncthreads();

    const int row0 = nb + wid * 16 + gq;
    const float* xg = x + (size_t)g * Nn * FIN;

    float acc[8][4];
    #pragma unroll
    for (int nt = 0; nt < 8; nt++)
        #pragma unroll
        for (int i = 0; i < 4; i++) acc[nt][i] = 0.f;

    #pragma unroll
    for (int c = 0; c < 4; c++) {
        const int kb = c * 16;
        float2 v00 = __ldg((const float2*)&xg[(size_t)(row0    ) * FIN + kb +     2 * t]);
        float2 v10 = __ldg((const float2*)&xg[(size_t)(row0 + 8) * FIN + kb +     2 * t]);
        float2 v01 = __ldg((const float2*)&xg[(size_t)(row0    ) * FIN + kb + 8 + 2 * t]);
        float2 v11 = __ldg((const float2*)&xg[(size_t)(row0 + 8) * FIN + kb + 8 + 2 * t]);
        uint32_t ahi[4], alo[4];
        cvt_hilo(v00, ahi[0], alo[0]);
        cvt_hilo(v10, ahi[1], alo[1]);
        cvt_hilo(v01, ahi[2], alo[2]);
        cvt_hilo(v11, ahi[3], alo[3]);

        #pragma unroll
        for (int nt = 0; nt < 8; nt++) {
            const int n = nt * 8 + gq;
            uint32_t bh0 = *(const uint32_t*)&Whi[n][kb +     2 * t];
            uint32_t bh1 = *(const uint32_t*)&Whi[n][kb + 8 + 2 * t];
            uint32_t bl0 = *(const uint32_t*)&Wlo[n][kb +     2 * t];
            uint32_t bl1 = *(const uint32_t*)&Wlo[n][kb + 8 + 2 * t];
            MMA16816(acc[nt], ahi, bh0, bh1);
            MMA16816(acc[nt], ahi, bl0, bl1);
            MMA16816(acc[nt], alo, bh0, bh1);
        }
    }

    // epilogue -> fp16 xw
    __half* op = g_xw + (size_t)g * NK;
    #pragma unroll
    for (int nt = 0; nt < 8; nt++) {
        const int col = nt * 8 + 2 * t;
        *(__half2*)&op[(size_t)(row0    ) * FOUT + col] =
            __floats2half2_rn(acc[nt][0], acc[nt][1]);
        *(__half2*)&op[(size_t)(row0 + 8) * FOUT + col] =
            __floats2half2_rn(acc[nt][2], acc[nt][3]);
    }
}

// ===========================================================================
// K2b: aggregation from global CSR, fp16 gather (128B/row). grid (G,4)x256.
// ===========================================================================
__global__ __launch_bounds__(256) void k2b_agg(const float* __restrict__ conv_bias)
{
    const int g   = blockIdx.x;
    const int q   = blockIdx.y;
    const int tid = threadIdx.x;
    const int wid  = tid >> 5;
    const int lane = tid & 31;

    const __half2* xw2  = (const __half2*)(g_xw + (size_t)g * NK);
    float2*       h2    = (float2*)      (g_h  + (size_t)g * NK);
    const int*    offx  = g_offx  + (size_t)g * (Nn + 1) + q * 128;
    const int*    srow  = g_srow  + (size_t)g * CSRE;
    const float*  snorm = g_snorm + (size_t)g * CSRE;

    const float bx0 = __ldg(&conv_bias[lane * 2]);
    const float bx1 = __ldg(&conv_bias[lane * 2 + 1]);

    for (int ln = wid; ln < 128; ln += 8) {
        const int n  = q * 128 + ln;
        const int b  = __ldg(&offx[ln]);
        const int e2 = __ldg(&offx[ln + 1]);

        float a0x = 0.f, a0y = 0.f, a1x = 0.f, a1y = 0.f;
        float a2x = 0.f, a2y = 0.f, a3x = 0.f, a3y = 0.f;
        int j = b;
        for (; j + 4 <= e2; j += 4) {
            int   r0 = __ldg(&srow[j]),    r1 = __ldg(&srow[j+1]);
            int   r2 = __ldg(&srow[j+2]),  r3 = __ldg(&srow[j+3]);
            float m0 = __ldg(&snorm[j]),   m1 = __ldg(&snorm[j+1]);
            float m2 = __ldg(&snorm[j+2]), m3 = __ldg(&snorm[j+3]);
            float2 v0 = __half22float2(xw2[r0 * 32 + lane]);
            float2 v1 = __half22float2(xw2[r1 * 32 + lane]);
            float2 v2 = __half22float2(xw2[r2 * 32 + lane]);
            float2 v3 = __half22float2(xw2[r3 * 32 + lane]);
            a0x = fmaf(v0.x, m0, a0x);  a0y = fmaf(v0.y, m0, a0y);
            a1x = fmaf(v1.x, m1, a1x);  a1y = fmaf(v1.y, m1, a1y);
            a2x = fmaf(v2.x, m2, a2x);  a2y = fmaf(v2.y, m2, a2y);
            a3x = fmaf(v3.x, m3, a3x);  a3y = fmaf(v3.y, m3, a3y);
        }
        for (; j < e2; j++) {
            int   r  = __ldg(&srow[j]);
            float nm = __ldg(&snorm[j]);
            float2 v = __half22float2(xw2[r * 32 + lane]);
            a0x = fmaf(v.x, nm, a0x);  a0y = fmaf(v.y, nm, a0y);
        }
        float ax = (a0x + a1x) + (a2x + a3x);
        float ay = (a0y + a1y) + (a2y + a3y);
        ax = fmaxf(ax + bx0, 0.f);
        ay = fmaxf(ay + bx1, 0.f);
        h2[n * 32 + lane] = make_float2(ax, ay);
    }
}

// ===========================================================================
// K3: logits = h @ lw^T + bias -> log_softmax (fused finish).
//     grid (KS, GT), block 256. smem-staged fp16 lw chunk (64KB).
//     Warp = 4 graphs x 512-k slice; exact smem reuse; last ksplit block
//     per gtile runs the softmax.
// ===========================================================================
__global__ __launch_bounds__(256) void k3_cls(const float* __restrict__ lb,
                                              float* __restrict__ out)
{
    extern __shared__ char sm3[];
    __half* slw  = (__half*)sm3;                 // [16][2048] halves (64KB)
    float*  red  = (float*)(sm3 + 65536);        // [8][4][16]
    int*    flag = (int*)(sm3 + 65536 + 2048);

    const int tid  = threadIdx.x;
    const int wid  = tid >> 5;
    const int lane = tid & 31;

    const int kb = blockIdx.x * 2048;            // chunk base (halves within NK)
    const int g0 = blockIdx.y * 8;

    // stage fp16 lw chunk: 16 classes x 2048 halves
    {
        uint4* dst = (uint4*)slw;
        for (int i = tid; i < 4096; i += 256) {
            int c = i >> 8, o = i & 255;
            dst[c * 256 + o] =
                ((const uint4*)(g_lwh + (size_t)c * NK + kb))[o];
        }
    }
    __syncthreads();

    const int ksl  = wid >> 1;                   // k slice 0..3 (512 halves)
    const int gsel = wid & 1;                    // graph group 0..1
    const int gb   = g0 + gsel * 4;

    float acc[4][Cc];
    #pragma unroll
    for (int gi = 0; gi < 4; gi++)
        #pragma unroll
        for (int c = 0; c < Cc; c++) acc[gi][c] = 0.f;

    #pragma unroll
    for (int j = 0; j < 4; j++) {
        const int koff = ksl * 512 + j * 128 + lane * 4;   // within chunk
        const int kg4  = (kb + koff) >> 2;                 // h float4 idx
        float4 hv[4];
        #pragma unroll
        for (int gi = 0; gi < 4; gi++)
            hv[gi] = __ldg((const float4*)(g_h + (size_t)(gb + gi) * NK) + kg4);

        #pragma unroll
        for (int c = 0; c < Cc; c++) {
            uint2 pw = *(const uint2*)&slw[c * 2048 + koff];
            float2 w0 = __half22float2(*(__half2*)&pw.x);
            float2 w1 = __half22float2(*(__half2*)&pw.y);
            #pragma unroll
            for (int gi = 0; gi < 4; gi++)
                acc[gi][c] = fmaf(hv[gi].x, w0.x, fmaf(hv[gi].y, w0.y,
                             fmaf(hv[gi].z, w1.x, fmaf(hv[gi].w, w1.y,
                                  acc[gi][c]))));
        }
    }

    // warp reduce each of 64 accs
    #pragma unroll
    for (int gi = 0; gi < 4; gi++)
        #pragma unroll
        for (int c = 0; c < Cc; c++) {
            float v = acc[gi][c];
            #pragma unroll
            for (int o = 16; o > 0; o >>= 1)
                v += __shfl_xor_sync(0xffffffffu, v, o);
            acc[gi][c] = v;
        }
    if (lane < Cc) {
        #pragma unroll
        for (int gi = 0; gi < 4; gi++)
            red[(wid * 4 + gi) * Cc + lane] = acc[gi][lane];
    }
    __syncthreads();

    // combine 4 k-slices -> atomic into g_logits
    if (tid < 128) {
        const int gi2 = tid >> 4;                // graph in block 0..7
        const int c   = tid & 15;
        const int gs  = gi2 >> 2;                // group
        const int gi  = gi2 & 3;
        float s = 0.f;
        #pragma unroll
        for (int k = 0; k < 4; k++)
            s += red[((k * 2 + gs) * 4 + gi) * Cc + c];
        atomicAdd(&g_logits[(size_t)(g0 + gi2) * Cc + c], s);
    }

    // completion: last ksplit block for this gtile runs softmax
    __threadfence();
    __syncthreads();
    if (tid == 0)
        *flag = (atomicAdd(&g_cnt[blockIdx.y], 1) == KS - 1) ? 1 : 0;
    __syncthreads();
    if (*flag && tid < 128) {
        __threadfence();
        const int g = g0 + (tid >> 4);
        const int c = tid & 15;
        float s = g_logits[(size_t)g * Cc + c] + __ldg(&lb[c]);
        float m = s;
        #pragma unroll
        for (int o = 8; o > 0; o >>= 1)
            m = fmaxf(m, __shfl_xor_sync(0xffffffffu, m, o, 16));
        float se = expf(s - m);
        #pragma unroll
        for (int o = 8; o > 0; o >>= 1)
            se += __shfl_xor_sync(0xffffffffu, se, o, 16);
        out[(size_t)g * Cc + c] = (s - m) - logf(se);
    }
}

// ===========================================================================
extern "C" void kernel_launch(void* const* d_in, const int* in_sizes, int n_in,
                              void* d_out, int out_size)
{
    const float* x  = (const float*)d_in[0];   // [G, N, F_IN]
    const int*   ei = (const int*)  d_in[1];   // [G, 2, E]
    const float* cw = (const float*)d_in[2];   // [F_OUT, F_IN]
    const float* cb = (const float*)d_in[3];   // [F_OUT]
    const float* lw = (const float*)d_in[4];   // [C, N*F_OUT]
    const float* lb = (const float*)d_in[5];   // [C]
    float* out = (float*)d_out;                // [G, C]

    static int inited = 0;
    const int k3_smem = 65536 + 2048 + 16;
    if (!inited) {
        cudaFuncSetAttribute(k3_cls, cudaFuncAttributeMaxDynamicSharedMemorySize,
                             k3_smem);
        inited = 1;
    }

    k0_csr <<<Gg, 512>>>(ei, lw);
    k1_mma <<<Gg * 4, 256>>>(x, cw);
    k2b_agg<<<dim3(Gg, 4), 256>>>(cb);
    k3_cls <<<dim3(KS, GT), 256, k3_smem>>>(lb, out);
}

// round 12
// speedup vs baseline: 1.4588x; 1.3627x over previous
#include <cuda_runtime.h>
#include <cuda_bf16.h>
#include <cuda_fp16.h>
#include <math.h>
#include <cstdint>

#define Gg   256
#define Nn   512
#define Ee   4096
#define FIN  64
#define FOUT 64
#define Cc   16
#define NK   (Nn * FOUT)          // 32768 flat features per graph
#define CSRE (Ee + Nn)            // 4608 CSR entries per graph
#define KS   16                   // k3 ksplit blocks
#define GT   16                   // k3 graph tiles (16 graphs each)

// ---------------- scratch ----------------
__device__ __half g_xw [(size_t)Gg * NK];          // x @ W^T   (fp16)
__device__ __half g_h16[(size_t)Gg * NK];          // relu(agg+bias) (fp16)
__device__ __half g_lwh[(size_t)Cc * NK];          // lin_weight fp16
__device__ int    g_srow [(size_t)Gg * CSRE];
__device__ float  g_snorm[(size_t)Gg * CSRE];
__device__ int    g_offx [(size_t)Gg * (Nn + 1)];
__device__ float  g_logits[(size_t)Gg * Cc];
__device__ int    g_cnt[GT];

// ===========================================================================
// MMA macros (baseline PTX, valid at compute_103)
// ===========================================================================
#define MMA_BF16(d, a, b0, b1)                                              \
    asm volatile("mma.sync.aligned.m16n8k16.row.col.f32.bf16.bf16.f32 "     \
        "{%0,%1,%2,%3}, {%4,%5,%6,%7}, {%8,%9}, {%0,%1,%2,%3};"             \
        : "+f"((d)[0]), "+f"((d)[1]), "+f"((d)[2]), "+f"((d)[3])            \
        : "r"((a)[0]), "r"((a)[1]), "r"((a)[2]), "r"((a)[3]),               \
          "r"(b0), "r"(b1))

#define MMA_F16(d, a0, a1, a2, a3, b0, b1)                                  \
    asm volatile("mma.sync.aligned.m16n8k16.row.col.f32.f16.f16.f32 "       \
        "{%0,%1,%2,%3}, {%4,%5,%6,%7}, {%8,%9}, {%0,%1,%2,%3};"             \
        : "+f"((d)[0]), "+f"((d)[1]), "+f"((d)[2]), "+f"((d)[3])            \
        : "r"(a0), "r"(a1), "r"(a2), "r"(a3), "r"(b0), "r"(b1))

__device__ __forceinline__ void cvt_hilo(float2 v, uint32_t& hi, uint32_t& lo)
{
    __nv_bfloat16 hx = __float2bfloat16_rn(v.x);
    __nv_bfloat16 hy = __float2bfloat16_rn(v.y);
    __nv_bfloat16 lx = __float2bfloat16_rn(v.x - __bfloat162float(hx));
    __nv_bfloat16 ly = __float2bfloat16_rn(v.y - __bfloat162float(hy));
    hi = (uint32_t)__bfloat16_as_ushort(hx) | ((uint32_t)__bfloat16_as_ushort(hy) << 16);
    lo = (uint32_t)__bfloat16_as_ushort(lx) | ((uint32_t)__bfloat16_as_ushort(ly) << 16);
}

// ===========================================================================
// kA (fat, 512 thr):
//   blocks [0, Gg)      : CSR build + lw fp16 convert + resets
//   blocks [Gg, Gg*3)   : xw = x @ W^T  (bf16 hi/lo mma.sync, 256 rows/blk)
// ===========================================================================
__global__ __launch_bounds__(512) void kA(const float* __restrict__ x,
                                          const float* __restrict__ w,
                                          const int*   __restrict__ ei,
                                          const float* __restrict__ lw)
{
    __shared__ __align__(16) char smu[18432];
    const int tid = threadIdx.x;

    if (blockIdx.x < Gg) {
        // -------- CSR build for graph g --------
        int*   cnt  = (int*)smu;
        int*   sc   = cnt + Nn;
        int*   wcur = sc + Nn;
        float* dv   = (float*)(wcur + Nn);

        const int g = blockIdx.x;
        const int* rowp = ei + (size_t)g * 2 * Ee;
        const int* colp = rowp + Ee;

        {   // lw -> fp16, slice per block
            const size_t base = (size_t)g * 2048;
            for (int i = tid; i < 2048; i += 512)
                g_lwh[base + i] = __float2half_rn(lw[base + i]);
        }
        if (g == 0 && tid < GT) g_cnt[tid] = 0;
        if (tid < Cc) g_logits[g * Cc + tid] = 0.f;

        cnt[tid] = 1;
        __syncthreads();
        for (int e = tid; e < Ee; e += 512)
            atomicAdd(&cnt[colp[e]], 1);
        __syncthreads();

        const int myc = cnt[tid];
        dv[tid] = rsqrtf((float)myc);
        sc[tid] = myc;
        __syncthreads();

        for (int s = 1; s < Nn; s <<= 1) {
            int v = (tid >= s) ? sc[tid - s] : 0;
            __syncthreads();
            sc[tid] += v;
            __syncthreads();
        }
        const int incl = sc[tid];
        const int excl = incl - myc;

        g_offx[(size_t)g * (Nn + 1) + tid + 1] = incl;
        if (tid == 0) g_offx[(size_t)g * (Nn + 1)] = 0;

        const size_t base = (size_t)g * CSRE;
        g_srow [base + excl] = tid;
        g_snorm[base + excl] = dv[tid] * dv[tid];
        wcur[tid] = excl + 1;
        __syncthreads();

        for (int e = tid; e < Ee; e += 512) {
            int r = rowp[e], c = colp[e];
            int pos = atomicAdd(&wcur[c], 1);
            g_srow [base + pos] = r;
            g_snorm[base + pos] = dv[r] * dv[c];
        }
    } else {
        // -------- GEMM: 256 rows x 64 outs, 16 warps x 16 rows --------
        __nv_bfloat16 (*Whi)[72] = (__nv_bfloat16(*)[72])smu;
        __nv_bfloat16 (*Wlo)[72] = (__nv_bfloat16(*)[72])(smu + 9216);

        const int wid  = tid >> 5;
        const int lane = tid & 31;
        const int gq   = lane >> 2;
        const int t    = lane & 3;

        const int b  = blockIdx.x - Gg;
        const int g  = b >> 1;
        const int nb = (b & 1) * 256;

        for (int i = tid; i < FOUT * FIN; i += 512) {
            int o = i >> 6, k = i & 63;
            float v = w[i];
            __nv_bfloat16 hb = __float2bfloat16_rn(v);
            Whi[o][k] = hb;
            Wlo[o][k] = __float2bfloat16_rn(v - __bfloat162float(hb));
        }
        __syncthreads();

        const int row0 = nb + wid * 16 + gq;
        const float* xg = x + (size_t)g * Nn * FIN;

        float acc[8][4];
        #pragma unroll
        for (int nt = 0; nt < 8; nt++)
            #pragma unroll
            for (int i = 0; i < 4; i++) acc[nt][i] = 0.f;

        #pragma unroll
        for (int c = 0; c < 4; c++) {
            const int kb = c * 16;
            float2 v00 = __ldg((const float2*)&xg[(size_t)(row0    ) * FIN + kb +     2 * t]);
            float2 v10 = __ldg((const float2*)&xg[(size_t)(row0 + 8) * FIN + kb +     2 * t]);
            float2 v01 = __ldg((const float2*)&xg[(size_t)(row0    ) * FIN + kb + 8 + 2 * t]);
            float2 v11 = __ldg((const float2*)&xg[(size_t)(row0 + 8) * FIN + kb + 8 + 2 * t]);
            uint32_t ahi[4], alo[4];
            cvt_hilo(v00, ahi[0], alo[0]);
            cvt_hilo(v10, ahi[1], alo[1]);
            cvt_hilo(v01, ahi[2], alo[2]);
            cvt_hilo(v11, ahi[3], alo[3]);

            #pragma unroll
            for (int nt = 0; nt < 8; nt++) {
                const int n = nt * 8 + gq;
                uint32_t bh0 = *(const uint32_t*)&Whi[n][kb +     2 * t];
                uint32_t bh1 = *(const uint32_t*)&Whi[n][kb + 8 + 2 * t];
                uint32_t bl0 = *(const uint32_t*)&Wlo[n][kb +     2 * t];
                uint32_t bl1 = *(const uint32_t*)&Wlo[n][kb + 8 + 2 * t];
                MMA_BF16(acc[nt], ahi, bh0, bh1);
                MMA_BF16(acc[nt], ahi, bl0, bl1);
                MMA_BF16(acc[nt], alo, bh0, bh1);
            }
        }

        __half* op = g_xw + (size_t)g * NK;
        #pragma unroll
        for (int nt = 0; nt < 8; nt++) {
            const int col = nt * 8 + 2 * t;
            *(__half2*)&op[(size_t)(row0    ) * FOUT + col] =
                __floats2half2_rn(acc[nt][0], acc[nt][1]);
            *(__half2*)&op[(size_t)(row0 + 8) * FOUT + col] =
                __floats2half2_rn(acc[nt][2], acc[nt][3]);
        }
    }
}

// ===========================================================================
// K2b: aggregation from global CSR, fp16 gather -> fp16 h. grid (G,4)x256.
// ===========================================================================
__global__ __launch_bounds__(256) void k2b_agg(const float* __restrict__ conv_bias)
{
    const int g   = blockIdx.x;
    const int q   = blockIdx.y;
    const int tid = threadIdx.x;
    const int wid  = tid >> 5;
    const int lane = tid & 31;

    const __half2* xw2  = (const __half2*)(g_xw  + (size_t)g * NK);
    __half2*       h2   = (__half2*)      (g_h16 + (size_t)g * NK);
    const int*    offx  = g_offx  + (size_t)g * (Nn + 1) + q * 128;
    const int*    srow  = g_srow  + (size_t)g * CSRE;
    const float*  snorm = g_snorm + (size_t)g * CSRE;

    const float bx0 = __ldg(&conv_bias[lane * 2]);
    const float bx1 = __ldg(&conv_bias[lane * 2 + 1]);

    for (int ln = wid; ln < 128; ln += 8) {
        const int n  = q * 128 + ln;
        const int b  = __ldg(&offx[ln]);
        const int e2 = __ldg(&offx[ln + 1]);

        float a0x = 0.f, a0y = 0.f, a1x = 0.f, a1y = 0.f;
        float a2x = 0.f, a2y = 0.f, a3x = 0.f, a3y = 0.f;
        int j = b;
        for (; j + 4 <= e2; j += 4) {
            int   r0 = __ldg(&srow[j]),    r1 = __ldg(&srow[j+1]);
            int   r2 = __ldg(&srow[j+2]),  r3 = __ldg(&srow[j+3]);
            float m0 = __ldg(&snorm[j]),   m1 = __ldg(&snorm[j+1]);
            float m2 = __ldg(&snorm[j+2]), m3 = __ldg(&snorm[j+3]);
            float2 v0 = __half22float2(xw2[r0 * 32 + lane]);
            float2 v1 = __half22float2(xw2[r1 * 32 + lane]);
            float2 v2 = __half22float2(xw2[r2 * 32 + lane]);
            float2 v3 = __half22float2(xw2[r3 * 32 + lane]);
            a0x = fmaf(v0.x, m0, a0x);  a0y = fmaf(v0.y, m0, a0y);
            a1x = fmaf(v1.x, m1, a1x);  a1y = fmaf(v1.y, m1, a1y);
            a2x = fmaf(v2.x, m2, a2x);  a2y = fmaf(v2.y, m2, a2y);
            a3x = fmaf(v3.x, m3, a3x);  a3y = fmaf(v3.y, m3, a3y);
        }
        for (; j < e2; j++) {
            int   r  = __ldg(&srow[j]);
            float nm = __ldg(&snorm[j]);
            float2 v = __half22float2(xw2[r * 32 + lane]);
            a0x = fmaf(v.x, nm, a0x);  a0y = fmaf(v.y, nm, a0y);
        }
        float ax = (a0x + a1x) + (a2x + a3x);
        float ay = (a0y + a1y) + (a2y + a3y);
        ax = fmaxf(ax + bx0, 0.f);
        ay = fmaxf(ay + bx1, 0.f);
        h2[n * 32 + lane] = __floats2half2_rn(ax, ay);
    }
}

// ===========================================================================
// K3: logits = h @ lw^T via f16 HMMA (fp32 acc) + fused bias/log_softmax.
//     grid (KS, GT), block 256 (8 warps). Warp = 16 graphs x 16 cls x K256.
// ===========================================================================
__global__ __launch_bounds__(256) void k3_cls(const float* __restrict__ lb,
                                              float* __restrict__ out)
{
    __shared__ float red[8][256];
    __shared__ int flag;

    const int tid  = threadIdx.x;
    const int wid  = tid >> 5;
    const int lane = tid & 31;
    const int grp  = lane >> 2;     // 0..7
    const int t    = lane & 3;      // 0..3

    const int kb = blockIdx.x * 2048;     // block K chunk (halves)
    const int g0 = blockIdx.y * 16;

    const int kw = kb + wid * 256;        // warp K slice

    float d0[4] = {0.f, 0.f, 0.f, 0.f};   // classes 0-7
    float d1[4] = {0.f, 0.f, 0.f, 0.f};   // classes 8-15

    const __half* ha = g_h16 + (size_t)(g0 + grp) * NK;
    const __half* hb = g_h16 + (size_t)(g0 + 8 + grp) * NK;
    const __half* w0 = g_lwh + (size_t)(grp) * NK;
    const __half* w1 = g_lwh + (size_t)(8 + grp) * NK;

    #pragma unroll 4
    for (int s = 0; s < 16; s++) {
        const int k = kw + s * 16 + 2 * t;
        uint32_t a0 = *(const uint32_t*)&ha[k];
        uint32_t a1 = *(const uint32_t*)&hb[k];
        uint32_t a2 = *(const uint32_t*)&ha[k + 8];
        uint32_t a3 = *(const uint32_t*)&hb[k + 8];
        uint32_t b00 = *(const uint32_t*)&w0[k];
        uint32_t b01 = *(const uint32_t*)&w0[k + 8];
        uint32_t b10 = *(const uint32_t*)&w1[k];
        uint32_t b11 = *(const uint32_t*)&w1[k + 8];
        MMA_F16(d0, a0, a1, a2, a3, b00, b01);
        MMA_F16(d1, a0, a1, a2, a3, b10, b11);
    }

    // scatter warp's 16x16 tile into red[wid]
    {
        float* r = red[wid];
        r[(grp    ) * 16 + 2 * t    ] = d0[0];
        r[(grp    ) * 16 + 2 * t + 1] = d0[1];
        r[(grp + 8) * 16 + 2 * t    ] = d0[2];
        r[(grp + 8) * 16 + 2 * t + 1] = d0[3];
        r[(grp    ) * 16 + 2 * t + 8] = d1[0];
        r[(grp    ) * 16 + 2 * t + 9] = d1[1];
        r[(grp + 8) * 16 + 2 * t + 8] = d1[2];
        r[(grp + 8) * 16 + 2 * t + 9] = d1[3];
    }
    __syncthreads();

    // combine 8 warps -> atomic into g_logits (tid = g*16 + c)
    {
        float s = 0.f;
        #pragma unroll
        for (int w = 0; w < 8; w++) s += red[w][tid];
        atomicAdd(&g_logits[(size_t)g0 * Cc + tid], s);
    }

    // completion: last ksplit block for this gtile runs softmax
    __threadfence();
    __syncthreads();
    if (tid == 0)
        flag = (atomicAdd(&g_cnt[blockIdx.y], 1) == KS - 1) ? 1 : 0;
    __syncthreads();
    if (flag) {
        __threadfence();
        const int g = g0 + (tid >> 4);
        const int c = tid & 15;
        float s = g_logits[(size_t)g * Cc + c] + __ldg(&lb[c]);
        float m = s;
        #pragma unroll
        for (int o = 8; o > 0; o >>= 1)
            m = fmaxf(m, __shfl_xor_sync(0xffffffffu, m, o, 16));
        float se = expf(s - m);
        #pragma unroll
        for (int o = 8; o > 0; o >>= 1)
            se += __shfl_xor_sync(0xffffffffu, se, o, 16);
        out[(size_t)g * Cc + c] = (s - m) - logf(se);
    }
}

// ===========================================================================
extern "C" void kernel_launch(void* const* d_in, const int* in_sizes, int n_in,
                              void* d_out, int out_size)
{
    const float* x  = (const float*)d_in[0];   // [G, N, F_IN]
    const int*   ei = (const int*)  d_in[1];   // [G, 2, E]
    const float* cw = (const float*)d_in[2];   // [F_OUT, F_IN]
    const float* cb = (const float*)d_in[3];   // [F_OUT]
    const float* lw = (const float*)d_in[4];   // [C, N*F_OUT]
    const float* lb = (const float*)d_in[5];   // [C]
    float* out = (float*)d_out;                // [G, C]

    kA     <<<Gg * 3, 512>>>(x, cw, ei, lw);
    k2b_agg<<<dim3(Gg, 4), 256>>>(cb);
    k3_cls <<<dim3(KS, GT), 256>>>(lb, out);
}

// round 13
// speedup vs baseline: 1.6745x; 1.1479x over previous
#include <cuda_runtime.h>
#include <cuda_bf16.h>
#include <cuda_fp16.h>
#include <math.h>
#include <cstdint>

#define Gg   256
#define Nn   512
#define Ee   4096
#define FIN  64
#define FOUT 64
#define Cc   16
#define NK   (Nn * FOUT)          // 32768 flat features per graph
#define CSRE (Ee + Nn)            // 4608 CSR entries per graph
#define KS   16                   // k3 ksplit blocks
#define GT   16                   // k3 graph tiles (16 graphs each)

// ---------------- scratch ----------------
__device__ __half g_xw [(size_t)Gg * NK];          // x @ W^T   (fp16)
__device__ __half g_h16[(size_t)Gg * NK];          // relu(agg+bias) (fp16)
__device__ __half g_lwh[(size_t)Cc * NK];          // lin_weight fp16
__device__ int    g_srow [(size_t)Gg * CSRE];
__device__ float  g_snorm[(size_t)Gg * CSRE];
__device__ int    g_offx [(size_t)Gg * (Nn + 1)];
__device__ float  g_logits[(size_t)Gg * Cc];
__device__ int    g_cnt[GT];

// ===========================================================================
// MMA macros (baseline PTX, valid at compute_103)
// ===========================================================================
#define MMA_BF16(d, a, b0, b1)                                              \
    asm volatile("mma.sync.aligned.m16n8k16.row.col.f32.bf16.bf16.f32 "     \
        "{%0,%1,%2,%3}, {%4,%5,%6,%7}, {%8,%9}, {%0,%1,%2,%3};"             \
        : "+f"((d)[0]), "+f"((d)[1]), "+f"((d)[2]), "+f"((d)[3])            \
        : "r"((a)[0]), "r"((a)[1]), "r"((a)[2]), "r"((a)[3]),               \
          "r"(b0), "r"(b1))

#define MMA_F16(d, a0, a1, a2, a3, b0, b1)                                  \
    asm volatile("mma.sync.aligned.m16n8k16.row.col.f32.f16.f16.f32 "       \
        "{%0,%1,%2,%3}, {%4,%5,%6,%7}, {%8,%9}, {%0,%1,%2,%3};"             \
        : "+f"((d)[0]), "+f"((d)[1]), "+f"((d)[2]), "+f"((d)[3])            \
        : "r"(a0), "r"(a1), "r"(a2), "r"(a3), "r"(b0), "r"(b1))

__device__ __forceinline__ void cvt_hilo(float2 v, uint32_t& hi, uint32_t& lo)
{
    __nv_bfloat16 hx = __float2bfloat16_rn(v.x);
    __nv_bfloat16 hy = __float2bfloat16_rn(v.y);
    __nv_bfloat16 lx = __float2bfloat16_rn(v.x - __bfloat162float(hx));
    __nv_bfloat16 ly = __float2bfloat16_rn(v.y - __bfloat162float(hy));
    hi = (uint32_t)__bfloat16_as_ushort(hx) | ((uint32_t)__bfloat16_as_ushort(hy) << 16);
    lo = (uint32_t)__bfloat16_as_ushort(lx) | ((uint32_t)__bfloat16_as_ushort(ly) << 16);
}

// ===========================================================================
// kA (fat, 512 thr):
//   blocks [0, Gg)      : CSR build + lw fp16 convert + resets
//   blocks [Gg, Gg*3)   : xw = x @ W^T  (bf16 hi/lo mma.sync, 256 rows/blk)
// ===========================================================================
__global__ __launch_bounds__(512) void kA(const float* __restrict__ x,
                                          const float* __restrict__ w,
                                          const int*   __restrict__ ei,
                                          const float* __restrict__ lw)
{
    __shared__ __align__(16) char smu[18432];
    const int tid = threadIdx.x;

    if (blockIdx.x < Gg) {
        // -------- CSR build for graph g --------
        int*   cnt  = (int*)smu;
        int*   sc   = cnt + Nn;
        int*   wcur = sc + Nn;
        float* dv   = (float*)(wcur + Nn);

        const int g = blockIdx.x;
        const int* rowp = ei + (size_t)g * 2 * Ee;
        const int* colp = rowp + Ee;

        {   // lw -> fp16, slice per block
            const size_t base = (size_t)g * 2048;
            for (int i = tid; i < 2048; i += 512)
                g_lwh[base + i] = __float2half_rn(lw[base + i]);
        }
        if (g == 0 && tid < GT) g_cnt[tid] = 0;
        if (tid < Cc) g_logits[g * Cc + tid] = 0.f;

        cnt[tid] = 1;
        __syncthreads();
        for (int e = tid; e < Ee; e += 512)
            atomicAdd(&cnt[colp[e]], 1);
        __syncthreads();

        const int myc = cnt[tid];
        dv[tid] = rsqrtf((float)myc);
        sc[tid] = myc;
        __syncthreads();

        for (int s = 1; s < Nn; s <<= 1) {
            int v = (tid >= s) ? sc[tid - s] : 0;
            __syncthreads();
            sc[tid] += v;
            __syncthreads();
        }
        const int incl = sc[tid];
        const int excl = incl - myc;

        g_offx[(size_t)g * (Nn + 1) + tid + 1] = incl;
        if (tid == 0) g_offx[(size_t)g * (Nn + 1)] = 0;

        const size_t base = (size_t)g * CSRE;
        g_srow [base + excl] = tid;
        g_snorm[base + excl] = dv[tid] * dv[tid];
        wcur[tid] = excl + 1;
        __syncthreads();

        for (int e = tid; e < Ee; e += 512) {
            int r = rowp[e], c = colp[e];
            int pos = atomicAdd(&wcur[c], 1);
            g_srow [base + pos] = r;
            g_snorm[base + pos] = dv[r] * dv[c];
        }
    } else {
        // -------- GEMM: 256 rows x 64 outs, 16 warps x 16 rows --------
        __nv_bfloat16 (*Whi)[72] = (__nv_bfloat16(*)[72])smu;
        __nv_bfloat16 (*Wlo)[72] = (__nv_bfloat16(*)[72])(smu + 9216);

        const int wid  = tid >> 5;
        const int lane = tid & 31;
        const int gq   = lane >> 2;
        const int t    = lane & 3;

        const int b  = blockIdx.x - Gg;
        const int g  = b >> 1;
        const int nb = (b & 1) * 256;

        for (int i = tid; i < FOUT * FIN; i += 512) {
            int o = i >> 6, k = i & 63;
            float v = w[i];
            __nv_bfloat16 hb = __float2bfloat16_rn(v);
            Whi[o][k] = hb;
            Wlo[o][k] = __float2bfloat16_rn(v - __bfloat162float(hb));
        }
        __syncthreads();

        const int row0 = nb + wid * 16 + gq;
        const float* xg = x + (size_t)g * Nn * FIN;

        float acc[8][4];
        #pragma unroll
        for (int nt = 0; nt < 8; nt++)
            #pragma unroll
            for (int i = 0; i < 4; i++) acc[nt][i] = 0.f;

        #pragma unroll
        for (int c = 0; c < 4; c++) {
            const int kb = c * 16;
            float2 v00 = __ldg((const float2*)&xg[(size_t)(row0    ) * FIN + kb +     2 * t]);
            float2 v10 = __ldg((const float2*)&xg[(size_t)(row0 + 8) * FIN + kb +     2 * t]);
            float2 v01 = __ldg((const float2*)&xg[(size_t)(row0    ) * FIN + kb + 8 + 2 * t]);
            float2 v11 = __ldg((const float2*)&xg[(size_t)(row0 + 8) * FIN + kb + 8 + 2 * t]);
            uint32_t ahi[4], alo[4];
            cvt_hilo(v00, ahi[0], alo[0]);
            cvt_hilo(v10, ahi[1], alo[1]);
            cvt_hilo(v01, ahi[2], alo[2]);
            cvt_hilo(v11, ahi[3], alo[3]);

            #pragma unroll
            for (int nt = 0; nt < 8; nt++) {
                const int n = nt * 8 + gq;
                uint32_t bh0 = *(const uint32_t*)&Whi[n][kb +     2 * t];
                uint32_t bh1 = *(const uint32_t*)&Whi[n][kb + 8 + 2 * t];
                uint32_t bl0 = *(const uint32_t*)&Wlo[n][kb +     2 * t];
                uint32_t bl1 = *(const uint32_t*)&Wlo[n][kb + 8 + 2 * t];
                MMA_BF16(acc[nt], ahi, bh0, bh1);
                MMA_BF16(acc[nt], ahi, bl0, bl1);
                MMA_BF16(acc[nt], alo, bh0, bh1);
            }
        }

        __half* op = g_xw + (size_t)g * NK;
        #pragma unroll
        for (int nt = 0; nt < 8; nt++) {
            const int col = nt * 8 + 2 * t;
            *(__half2*)&op[(size_t)(row0    ) * FOUT + col] =
                __floats2half2_rn(acc[nt][0], acc[nt][1]);
            *(__half2*)&op[(size_t)(row0 + 8) * FOUT + col] =
                __floats2half2_rn(acc[nt][2], acc[nt][3]);
        }
    }
}

// ===========================================================================
// K2b: one block per graph. Stage xw[g] (64KB fp16) in smem; all 4608
//      gathers hit LDS (conflict-free: bank = lane). grid G x 512 thr.
// ===========================================================================
__global__ __launch_bounds__(512) void k2b_agg(const float* __restrict__ conv_bias)
{
    extern __shared__ __align__(16) __half2 xs[];   // [512 rows][32 half2] = 64KB

    const int g   = blockIdx.x;
    const int tid = threadIdx.x;
    const int wid  = tid >> 5;
    const int lane = tid & 31;

    // stage xw[g]: 4096 uint4, 8 per thread, coalesced
    {
        const uint4* src = (const uint4*)(g_xw + (size_t)g * NK);
        uint4* dst = (uint4*)xs;
        #pragma unroll
        for (int i = 0; i < 8; i++)
            dst[i * 512 + tid] = __ldg(&src[i * 512 + tid]);
    }

    const int*   offx  = g_offx  + (size_t)g * (Nn + 1);
    const int*   srow  = g_srow  + (size_t)g * CSRE;
    const float* snorm = g_snorm + (size_t)g * CSRE;
    __half2*     h2    = (__half2*)(g_h16 + (size_t)g * NK);

    const float bx0 = __ldg(&conv_bias[lane * 2]);
    const float bx1 = __ldg(&conv_bias[lane * 2 + 1]);
    __syncthreads();

    for (int n = wid; n < Nn; n += 16) {
        const int b  = __ldg(&offx[n]);
        const int e2 = __ldg(&offx[n + 1]);

        float a0x = 0.f, a0y = 0.f, a1x = 0.f, a1y = 0.f;
        float a2x = 0.f, a2y = 0.f, a3x = 0.f, a3y = 0.f;
        int j = b;
        for (; j + 4 <= e2; j += 4) {
            int   r0 = __ldg(&srow[j]),    r1 = __ldg(&srow[j+1]);
            int   r2 = __ldg(&srow[j+2]),  r3 = __ldg(&srow[j+3]);
            float m0 = __ldg(&snorm[j]),   m1 = __ldg(&snorm[j+1]);
            float m2 = __ldg(&snorm[j+2]), m3 = __ldg(&snorm[j+3]);
            float2 v0 = __half22float2(xs[r0 * 32 + lane]);
            float2 v1 = __half22float2(xs[r1 * 32 + lane]);
            float2 v2 = __half22float2(xs[r2 * 32 + lane]);
            float2 v3 = __half22float2(xs[r3 * 32 + lane]);
            a0x = fmaf(v0.x, m0, a0x);  a0y = fmaf(v0.y, m0, a0y);
            a1x = fmaf(v1.x, m1, a1x);  a1y = fmaf(v1.y, m1, a1y);
            a2x = fmaf(v2.x, m2, a2x);  a2y = fmaf(v2.y, m2, a2y);
            a3x = fmaf(v3.x, m3, a3x);  a3y = fmaf(v3.y, m3, a3y);
        }
        for (; j < e2; j++) {
            int   r  = __ldg(&srow[j]);
            float nm = __ldg(&snorm[j]);
            float2 v = __half22float2(xs[r * 32 + lane]);
            a0x = fmaf(v.x, nm, a0x);  a0y = fmaf(v.y, nm, a0y);
        }
        float ax = (a0x + a1x) + (a2x + a3x);
        float ay = (a0y + a1y) + (a2y + a3y);
        ax = fmaxf(ax + bx0, 0.f);
        ay = fmaxf(ay + bx1, 0.f);
        h2[n * 32 + lane] = __floats2half2_rn(ax, ay);
    }
}

// ===========================================================================
// K3: logits = h @ lw^T via f16 HMMA (fp32 acc) + fused bias/log_softmax.
//     grid (KS, GT), block 256 (8 warps). Warp = 16 graphs x 16 cls x K256.
// ===========================================================================
__global__ __launch_bounds__(256) void k3_cls(const float* __restrict__ lb,
                                              float* __restrict__ out)
{
    __shared__ float red[8][256];
    __shared__ int flag;

    const int tid  = threadIdx.x;
    const int wid  = tid >> 5;
    const int lane = tid & 31;
    const int grp  = lane >> 2;     // 0..7
    const int t    = lane & 3;      // 0..3

    const int kb = blockIdx.x * 2048;     // block K chunk (halves)
    const int g0 = blockIdx.y * 16;

    const int kw = kb + wid * 256;        // warp K slice

    float d0[4] = {0.f, 0.f, 0.f, 0.f};   // classes 0-7
    float d1[4] = {0.f, 0.f, 0.f, 0.f};   // classes 8-15

    const __half* ha = g_h16 + (size_t)(g0 + grp) * NK;
    const __half* hb = g_h16 + (size_t)(g0 + 8 + grp) * NK;
    const __half* w0 = g_lwh + (size_t)(grp) * NK;
    const __half* w1 = g_lwh + (size_t)(8 + grp) * NK;

    #pragma unroll 4
    for (int s = 0; s < 16; s++) {
        const int k = kw + s * 16 + 2 * t;
        uint32_t a0 = *(const uint32_t*)&ha[k];
        uint32_t a1 = *(const uint32_t*)&hb[k];
        uint32_t a2 = *(const uint32_t*)&ha[k + 8];
        uint32_t a3 = *(const uint32_t*)&hb[k + 8];
        uint32_t b00 = *(const uint32_t*)&w0[k];
        uint32_t b01 = *(const uint32_t*)&w0[k + 8];
        uint32_t b10 = *(const uint32_t*)&w1[k];
        uint32_t b11 = *(const uint32_t*)&w1[k + 8];
        MMA_F16(d0, a0, a1, a2, a3, b00, b01);
        MMA_F16(d1, a0, a1, a2, a3, b10, b11);
    }

    // scatter warp's 16x16 tile into red[wid]
    {
        float* r = red[wid];
        r[(grp    ) * 16 + 2 * t    ] = d0[0];
        r[(grp    ) * 16 + 2 * t + 1] = d0[1];
        r[(grp + 8) * 16 + 2 * t    ] = d0[2];
        r[(grp + 8) * 16 + 2 * t + 1] = d0[3];
        r[(grp    ) * 16 + 2 * t + 8] = d1[0];
        r[(grp    ) * 16 + 2 * t + 9] = d1[1];
        r[(grp + 8) * 16 + 2 * t + 8] = d1[2];
        r[(grp + 8) * 16 + 2 * t + 9] = d1[3];
    }
    __syncthreads();

    // combine 8 warps -> atomic into g_logits (tid = g*16 + c)
    {
        float s = 0.f;
        #pragma unroll
        for (int w = 0; w < 8; w++) s += red[w][tid];
        atomicAdd(&g_logits[(size_t)g0 * Cc + tid], s);
    }

    // completion: last ksplit block for this gtile runs softmax
    __threadfence();
    __syncthreads();
    if (tid == 0)
        flag = (atomicAdd(&g_cnt[blockIdx.y], 1) == KS - 1) ? 1 : 0;
    __syncthreads();
    if (flag) {
        __threadfence();
        const int g = g0 + (tid >> 4);
        const int c = tid & 15;
        float s = g_logits[(size_t)g * Cc + c] + __ldg(&lb[c]);
        float m = s;
        #pragma unroll
        for (int o = 8; o > 0; o >>= 1)
            m = fmaxf(m, __shfl_xor_sync(0xffffffffu, m, o, 16));
        float se = expf(s - m);
        #pragma unroll
        for (int o = 8; o > 0; o >>= 1)
            se += __shfl_xor_sync(0xffffffffu, se, o, 16);
        out[(size_t)g * Cc + c] = (s - m) - logf(se);
    }
}

// ===========================================================================
extern "C" void kernel_launch(void* const* d_in, const int* in_sizes, int n_in,
                              void* d_out, int out_size)
{
    const float* x  = (const float*)d_in[0];   // [G, N, F_IN]
    const int*   ei = (const int*)  d_in[1];   // [G, 2, E]
    const float* cw = (const float*)d_in[2];   // [F_OUT, F_IN]
    const float* cb = (const float*)d_in[3];   // [F_OUT]
    const float* lw = (const float*)d_in[4];   // [C, N*F_OUT]
    const float* lb = (const float*)d_in[5];   // [C]
    float* out = (float*)d_out;                // [G, C]

    const int k2_smem = 65536;
    cudaFuncSetAttribute(k2b_agg, cudaFuncAttributeMaxDynamicSharedMemorySize,
                         k2_smem);

    kA     <<<Gg * 3, 512>>>(x, cw, ei, lw);
    k2b_agg<<<Gg, 512, k2_smem>>>(cb);
    k3_cls <<<dim3(KS, GT), 256>>>(lb, out);
}

// round 16
// speedup vs baseline: 2.0689x; 1.2355x over previous
#include <cuda_runtime.h>
#include <cuda_bf16.h>
#include <cuda_fp16.h>
#include <math.h>
#include <cstdint>

#define Gg   256
#define Nn   512
#define Ee   4096
#define FIN  64
#define FOUT 64
#define Cc   16
#define NK   (Nn * FOUT)          // 32768 flat features per graph
#define CSRE (Ee + Nn)            // 4608 CSR entries per graph
#define KS   16                   // k3 ksplit blocks
#define GT   16                   // k3 graph tiles (16 graphs each)

// ---------------- scratch ----------------
__device__ __half g_xw [(size_t)Gg * NK];          // x @ W^T   (fp16)
__device__ __half g_h16[(size_t)Gg * NK];          // relu(agg+bias) (fp16)
__device__ __half g_lwh[(size_t)Cc * NK];          // lin_weight fp16
__device__ float  g_logits[(size_t)Gg * Cc];
__device__ int    g_cnt[GT];

// ===========================================================================
// MMA macros (baseline PTX, valid at compute_103)
// ===========================================================================
#define MMA_BF16(d, a0, a1, a2, a3, b0, b1)                                 \
    asm volatile("mma.sync.aligned.m16n8k16.row.col.f32.bf16.bf16.f32 "     \
        "{%0,%1,%2,%3}, {%4,%5,%6,%7}, {%8,%9}, {%0,%1,%2,%3};"             \
        : "+f"((d)[0]), "+f"((d)[1]), "+f"((d)[2]), "+f"((d)[3])            \
        : "r"(a0), "r"(a1), "r"(a2), "r"(a3), "r"(b0), "r"(b1))

#define MMA_F16(d, a0, a1, a2, a3, b0, b1)                                  \
    asm volatile("mma.sync.aligned.m16n8k16.row.col.f32.f16.f16.f32 "       \
        "{%0,%1,%2,%3}, {%4,%5,%6,%7}, {%8,%9}, {%0,%1,%2,%3};"             \
        : "+f"((d)[0]), "+f"((d)[1]), "+f"((d)[2]), "+f"((d)[3])            \
        : "r"(a0), "r"(a1), "r"(a2), "r"(a3), "r"(b0), "r"(b1))

// pack two f32 -> bf16x2 in ONE op: result = {lo = vlo, hi = vhi}
__device__ __forceinline__ uint32_t cvt2bf(float vhi, float vlo)
{
    uint32_t r;
    asm("cvt.rn.bf16x2.f32 %0, %1, %2;" : "=r"(r) : "f"(vhi), "f"(vlo));
    return r;
}

// ===========================================================================
// kA: pure GEMM  xw = x @ W^T, single-pass bf16 mma.sync, 256 rows/block.
//     Also converts its lw slice to fp16.  512 blocks x 512 thr.
// ===========================================================================
__global__ __launch_bounds__(512) void kA(const float* __restrict__ x,
                                          const float* __restrict__ w,
                                          const float* __restrict__ lw)
{
    __shared__ __align__(16) __nv_bfloat16 Wb[FOUT][72];   // 9216 B

    const int tid  = threadIdx.x;
    const int wid  = tid >> 5;
    const int lane = tid & 31;
    const int gq   = lane >> 2;
    const int t    = lane & 3;

    const int g  = blockIdx.x >> 1;
    const int nb = (blockIdx.x & 1) * 256;

    // lw -> fp16, slice per block (512 blocks x 1024 elems = full 524288)
    {
        const size_t base = (size_t)blockIdx.x * 1024;
        for (int i = tid; i < 1024; i += 512)
            g_lwh[base + i] = __float2half_rn(lw[base + i]);
    }

    for (int i = tid; i < FOUT * FIN; i += 512) {
        int o = i >> 6, k = i & 63;
        Wb[o][k] = __float2bfloat16_rn(w[i]);
    }
    __syncthreads();

    const int row0 = nb + wid * 16 + gq;
    const float* xg = x + (size_t)g * Nn * FIN;

    float acc[8][4];
    #pragma unroll
    for (int nt = 0; nt < 8; nt++)
        #pragma unroll
        for (int i = 0; i < 4; i++) acc[nt][i] = 0.f;

    #pragma unroll
    for (int c = 0; c < 4; c++) {
        const int kb = c * 16;
        float2 v00 = __ldg((const float2*)&xg[(size_t)(row0    ) * FIN + kb +     2 * t]);
        float2 v10 = __ldg((const float2*)&xg[(size_t)(row0 + 8) * FIN + kb +     2 * t]);
        float2 v01 = __ldg((const float2*)&xg[(size_t)(row0    ) * FIN + kb + 8 + 2 * t]);
        float2 v11 = __ldg((const float2*)&xg[(size_t)(row0 + 8) * FIN + kb + 8 + 2 * t]);
        uint32_t a0 = cvt2bf(v00.y, v00.x);
        uint32_t a1 = cvt2bf(v10.y, v10.x);
        uint32_t a2 = cvt2bf(v01.y, v01.x);
        uint32_t a3 = cvt2bf(v11.y, v11.x);

        #pragma unroll
        for (int nt = 0; nt < 8; nt++) {
            const int n = nt * 8 + gq;
            uint32_t b0 = *(const uint32_t*)&Wb[n][kb +     2 * t];
            uint32_t b1 = *(const uint32_t*)&Wb[n][kb + 8 + 2 * t];
            MMA_BF16(acc[nt], a0, a1, a2, a3, b0, b1);
        }
    }

    __half* op = g_xw + (size_t)g * NK;
    #pragma unroll
    for (int nt = 0; nt < 8; nt++) {
        const int col = nt * 8 + 2 * t;
        *(__half2*)&op[(size_t)(row0    ) * FOUT + col] =
            __floats2half2_rn(acc[nt][0], acc[nt][1]);
        *(__half2*)&op[(size_t)(row0 + 8) * FOUT + col] =
            __floats2half2_rn(acc[nt][2], acc[nt][3]);
    }
}

// ===========================================================================
// K2b: one block per graph. Stage xw[g] (64KB fp16) + build CSR in smem +
//      aggregate + bias + ReLU -> fp16 h. No global CSR. 512 thr.
// ===========================================================================
#define K2_SMEM (65536 + CSRE * 8 + Nn * 16 + 2112)

__global__ __launch_bounds__(512) void k2b_agg(const int*   __restrict__ ei,
                                               const float* __restrict__ conv_bias)
{
    extern __shared__ __align__(16) char sm2[];
    __half2* xs    = (__half2*)sm2;                          // 65536 B
    int*     srow  = (int*)  (sm2 + 65536);                  // 18432 B
    float*   snorm = (float*)(sm2 + 65536 + 18432);          // 18432 B
    int*     cnt   = (int*)  (sm2 + 65536 + 36864);          // 2048 B
    float*   dv    = (float*)(sm2 + 65536 + 38912);          // 2048 B
    int*     wcur  = (int*)  (sm2 + 65536 + 40960);          // 2048 B
    int*     offx  = (int*)  (sm2 + 65536 + 43008);          // 2064 B

    const int g   = blockIdx.x;
    const int tid = threadIdx.x;
    const int wid  = tid >> 5;
    const int lane = tid & 31;

    // ---- stage xw[g]: 4096 uint4, 8 per thread, coalesced ----
    {
        const uint4* src = (const uint4*)(g_xw + (size_t)g * NK);
        uint4* dst = (uint4*)xs;
        #pragma unroll
        for (int i = 0; i < 8; i++)
            dst[i * 512 + tid] = __ldg(&src[i * 512 + tid]);
    }

    const int* rowp = ei + (size_t)g * 2 * Ee;
    const int* colp = rowp + Ee;

    // ---- CSR build in smem ----
    cnt[tid] = 1;                          // self-loop
    __syncthreads();
    for (int e = tid; e < Ee; e += 512)
        atomicAdd(&cnt[colp[e]], 1);
    __syncthreads();

    const int myc = cnt[tid];
    dv[tid]   = rsqrtf((float)myc);
    wcur[tid] = myc;                       // scan buffer
    __syncthreads();

    for (int s = 1; s < Nn; s <<= 1) {
        int v = (tid >= s) ? wcur[tid - s] : 0;
        __syncthreads();
        wcur[tid] += v;
        __syncthreads();
    }
    const int incl = wcur[tid];
    const int excl = incl - myc;
    offx[tid + 1] = incl;
    if (tid == 0) offx[0] = 0;
    srow[excl]  = tid;                     // self-loop entry first
    snorm[excl] = dv[tid] * dv[tid];
    cnt[tid] = excl + 1;                   // write cursor
    if (tid < Cc) g_logits[(size_t)g * Cc + tid] = 0.f;
    if (g < GT && tid == 0) g_cnt[g] = 0;
    __syncthreads();

    for (int e = tid; e < Ee; e += 512) {
        int r = rowp[e], c = colp[e];
        int pos = atomicAdd(&cnt[c], 1);
        srow[pos]  = r;
        snorm[pos] = dv[r] * dv[c];
    }
    __syncthreads();

    // ---- aggregate: warp-per-node, all gathers hit LDS ----
    __half2* h2 = (__half2*)(g_h16 + (size_t)g * NK);
    const float bx0 = __ldg(&conv_bias[lane * 2]);
    const float bx1 = __ldg(&conv_bias[lane * 2 + 1]);

    for (int n = wid; n < Nn; n += 16) {
        const int b  = offx[n];
        const int e2 = offx[n + 1];

        float a0x = 0.f, a0y = 0.f, a1x = 0.f, a1y = 0.f;
        float a2x = 0.f, a2y = 0.f, a3x = 0.f, a3y = 0.f;
        int j = b;
        for (; j + 4 <= e2; j += 4) {
            int   r0 = srow[j],   r1 = srow[j+1], r2 = srow[j+2], r3 = srow[j+3];
            float m0 = snorm[j],  m1 = snorm[j+1], m2 = snorm[j+2], m3 = snorm[j+3];
            float2 v0 = __half22float2(xs[r0 * 32 + lane]);
            float2 v1 = __half22float2(xs[r1 * 32 + lane]);
            float2 v2 = __half22float2(xs[r2 * 32 + lane]);
            float2 v3 = __half22float2(xs[r3 * 32 + lane]);
            a0x = fmaf(v0.x, m0, a0x);  a0y = fmaf(v0.y, m0, a0y);
            a1x = fmaf(v1.x, m1, a1x);  a1y = fmaf(v1.y, m1, a1y);
            a2x = fmaf(v2.x, m2, a2x);  a2y = fmaf(v2.y, m2, a2y);
            a3x = fmaf(v3.x, m3, a3x);  a3y = fmaf(v3.y, m3, a3y);
        }
        for (; j < e2; j++) {
            int   r  = srow[j];
            float nm = snorm[j];
            float2 v = __half22float2(xs[r * 32 + lane]);
            a0x = fmaf(v.x, nm, a0x);  a0y = fmaf(v.y, nm, a0y);
        }
        float ax = (a0x + a1x) + (a2x + a3x);
        float ay = (a0y + a1y) + (a2y + a3y);
        ax = fmaxf(ax + bx0, 0.f);
        ay = fmaxf(ay + bx1, 0.f);
        h2[n * 32 + lane] = __floats2half2_rn(ax, ay);
    }
}

// ===========================================================================
// K3: logits = h @ lw^T via f16 HMMA (fp32 acc) + fused bias/log_softmax.
//     grid (KS, GT), block 256 (8 warps). Warp = 16 graphs x 16 cls x K256.
// ===========================================================================
__global__ __launch_bounds__(256) void k3_cls(const float* __restrict__ lb,
                                              float* __restrict__ out)
{
    __shared__ float red[8][256];
    __shared__ int flag;

    const int tid  = threadIdx.x;
    const int wid  = tid >> 5;
    const int lane = tid & 31;
    const int grp  = lane >> 2;     // 0..7
    const int t    = lane & 3;      // 0..3

    const int kb = blockIdx.x * 2048;     // block K chunk (halves)
    const int g0 = blockIdx.y * 16;

    const int kw = kb + wid * 256;        // warp K slice

    float d0[4] = {0.f, 0.f, 0.f, 0.f};   // classes 0-7
    float d1[4] = {0.f, 0.f, 0.f, 0.f};   // classes 8-15

    const __half* ha = g_h16 + (size_t)(g0 + grp) * NK;
    const __half* hb = g_h16 + (size_t)(g0 + 8 + grp) * NK;
    const __half* w0 = g_lwh + (size_t)(grp) * NK;
    const __half* w1 = g_lwh + (size_t)(8 + grp) * NK;

    #pragma unroll 4
    for (int s = 0; s < 16; s++) {
        const int k = kw + s * 16 + 2 * t;
        uint32_t a0 = *(const uint32_t*)&ha[k];
        uint32_t a1 = *(const uint32_t*)&hb[k];
        uint32_t a2 = *(const uint32_t*)&ha[k + 8];
        uint32_t a3 = *(const uint32_t*)&hb[k + 8];
        uint32_t b00 = *(const uint32_t*)&w0[k];
        uint32_t b01 = *(const uint32_t*)&w0[k + 8];
        uint32_t b10 = *(const uint32_t*)&w1[k];
        uint32_t b11 = *(const uint32_t*)&w1[k + 8];
        MMA_F16(d0, a0, a1, a2, a3, b00, b01);
        MMA_F16(d1, a0, a1, a2, a3, b10, b11);
    }

    // scatter warp's 16x16 tile into red[wid]
    {
        float* r = red[wid];
        r[(grp    ) * 16 + 2 * t    ] = d0[0];
        r[(grp    ) * 16 + 2 * t + 1] = d0[1];
        r[(grp + 8) * 16 + 2 * t    ] = d0[2];
        r[(grp + 8) * 16 + 2 * t + 1] = d0[3];
        r[(grp    ) * 16 + 2 * t + 8] = d1[0];
        r[(grp    ) * 16 + 2 * t + 9] = d1[1];
        r[(grp + 8) * 16 + 2 * t + 8] = d1[2];
        r[(grp + 8) * 16 + 2 * t + 9] = d1[3];
    }
    __syncthreads();

    // combine 8 warps -> atomic into g_logits (tid = g*16 + c)
    {
        float s = 0.f;
        #pragma unroll
        for (int w = 0; w < 8; w++) s += red[w][tid];
        atomicAdd(&g_logits[(size_t)g0 * Cc + tid], s);
    }

    // completion: last ksplit block for this gtile runs softmax
    __threadfence();
    __syncthreads();
    if (tid == 0)
        flag = (atomicAdd(&g_cnt[blockIdx.y], 1) == KS - 1) ? 1 : 0;
    __syncthreads();
    if (flag) {
        __threadfence();
        const int g = g0 + (tid >> 4);
        const int c = tid & 15;
        float s = g_logits[(size_t)g * Cc + c] + __ldg(&lb[c]);
        float m = s;
        #pragma unroll
        for (int o = 8; o > 0; o >>= 1)
            m = fmaxf(m, __shfl_xor_sync(0xffffffffu, m, o, 16));
        float se = expf(s - m);
        #pragma unroll
        for (int o = 8; o > 0; o >>= 1)
            se += __shfl_xor_sync(0xffffffffu, se, o, 16);
        out[(size_t)g * Cc + c] = (s - m) - logf(se);
    }
}

// ===========================================================================
extern "C" void kernel_launch(void* const* d_in, const int* in_sizes, int n_in,
                              void* d_out, int out_size)
{
    const float* x  = (const float*)d_in[0];   // [G, N, F_IN]
    const int*   ei = (const int*)  d_in[1];   // [G, 2, E]
    const float* cw = (const float*)d_in[2];   // [F_OUT, F_IN]
    const float* cb = (const float*)d_in[3];   // [F_OUT]
    const float* lw = (const float*)d_in[4];   // [C, N*F_OUT]
    const float* lb = (const float*)d_in[5];   // [C]
    float* out = (float*)d_out;                // [G, C]

    // do-once: keep attribute call out of the graph-capture pass (R8 pattern)
    static bool inited = false;
    if (!inited) {
        cudaFuncSetAttribute(k2b_agg,
                             cudaFuncAttributeMaxDynamicSharedMemorySize,
                             K2_SMEM);
        inited = true;
    }

    kA     <<<Gg * 2, 512>>>(x, cw, lw);
    k2b_agg<<<Gg, 512, K2_SMEM>>>(ei, cb);
    k3_cls <<<dim3(KS, GT), 256>>>(lb, out);
}